// round 14
// baseline (speedup 1.0000x reference)
#include <cuda_runtime.h>
#include <math.h>

#define BB 2
#define PP 50000
#define FF 100000
#define HH 1024
#define WW 1024
#define TH 1024
#define TW 1024

// Per-face feature struct: 4 x float4 = 64 bytes.
// [0]: p0.x p0.y p0.z p1.x
// [1]: p1.y p1.z p2.x p2.y
// [2]: p2.z u0.x u0.y u1.x
// [3]: u1.y u2.x u2.y pad
__device__ float4 g_face[BB * FF * 4];
// Interleaved texture: rgba per texel, 16B.
__device__ float4 g_tex4[BB * TH * TW];
// Per-batch packed constants.
__device__ float4 g_bconst[BB * 4];
// Generation-based barrier counter (monotonic across launches; no reset).
__device__ unsigned int g_bar;

#define NPIX (BB * HH * WW)                   // 2097152
#define FACE_N (BB * FF)
#define FACE_BLOCKS ((FACE_N + 255) / 256)    // 782
#define INTERLEAVE_VB (NPIX / 1024)           // 2048 (1024 texels per vblock)
#define PREP_VB (FACE_BLOCKS + INTERLEAVE_VB) // 2830
#define PIXEL_VB (NPIX / 256)                 // 8192
#define GRID_BLOCKS 592                       // 148 SMs x 4 resident blocks

// Exact nearest texel index chain; every multiply is by a power of two so this
// is contraction-insensitive.
__device__ __forceinline__ float texindex(float x, float T) {
    float t = __fadd_rn(x, 1.0f);
    t = __fmul_rn(t, T);
    t = __fsub_rn(t, 1.0f);
    t = __fmul_rn(t, 0.5f);
    t = __fadd_rn(t, 0.5f);
    return floorf(t);
}

__global__ void __launch_bounds__(256, 4) fused_kernel(
    const float* __restrict__ points,   // (B,P,3)
    const int*   __restrict__ faces,    // (F,3)
    const float* __restrict__ rot,      // (B,3,3)
    const float* __restrict__ cpos,     // (B,3)
    const float* __restrict__ uv,       // (B,P,2)
    const float* __restrict__ texture,  // (B,3,TH,TW)
    const float* __restrict__ light,    // (B,3)
    const float* __restrict__ material, // (B,3,3)
    const float* __restrict__ shininess,// (B,1)
    const int*   __restrict__ pixface,  // (B,H,W)
    const float* __restrict__ pixw,     // (B,H,W,3)
    const float* __restrict__ improb,   // (B,H,W,1)
    float* __restrict__ out)            // flat
{
    const int tid = threadIdx.x;
    const int lane = tid & 31;
    const int warp = tid >> 5;
    float* out_normal = out + (size_t)NPIX * 3 + NPIX;

    // ================= PHASE 1: prep (faces + texture interleave) ==========
    for (int vb = blockIdx.x; vb < PREP_VB; vb += GRID_BLOCKS) {
        if (vb >= FACE_BLOCKS) {
            // texture interleave, fully coalesced, 4 texels/thread
            int base = (vb - FACE_BLOCKS) * 1024 + tid;
#pragma unroll
            for (int k = 0; k < 4; k++) {
                int t = base + k * 256;
                int b = t >> 20;
                int pos = t & (TH * TW - 1);
                size_t pbase = (size_t)b * 3 * TH * TW + pos;
                float r = __ldcs(texture + pbase);
                float g = __ldcs(texture + pbase + (size_t)TH * TW);
                float bl = __ldcs(texture + pbase + 2 * (size_t)TH * TW);
                g_tex4[t] = make_float4(r, g, bl, 0.0f);
            }
            continue;
        }

        int idx = vb * 256 + tid;

        if (vb == 0 && tid >= 256 - BB) {
            int b = tid - (256 - BB);
            float lx = light[b * 3 + 0], ly = light[b * 3 + 1], lz = light[b * 3 + 2];
            float llen = sqrtf(lx * lx + ly * ly + lz * lz + 1e-8f) + 1e-15f;
            float linv = 1.0f / llen;
            const float* M = material + b * 9;
            g_bconst[b * 4 + 0] = make_float4(M[0], M[1], M[2], shininess[b]);
            g_bconst[b * 4 + 1] = make_float4(M[3], M[4], M[5], 0.0f);
            g_bconst[b * 4 + 2] = make_float4(M[6], M[7], M[8], 0.0f);
            g_bconst[b * 4 + 3] = make_float4(lx * linv, ly * linv, lz * linv, 0.0f);
        }

        if (idx >= FACE_N) continue;
        int b = idx / FF;
        int f = idx - b * FF;

        int i0 = __ldcs(faces + f * 3 + 0);
        int i1 = __ldcs(faces + f * 3 + 1);
        int i2 = __ldcs(faces + f * 3 + 2);

        float cx = cpos[b * 3 + 0], cy = cpos[b * 3 + 1], cz = cpos[b * 3 + 2];
        const float* R = rot + b * 9;
        float r0 = R[0], r1 = R[1], r2 = R[2];
        float r3 = R[3], r4 = R[4], r5 = R[5];
        float r6 = R[6], r7 = R[7], r8 = R[8];

        float px[3], py[3], pz[3];
        int vidx[3] = {i0, i1, i2};
#pragma unroll
        for (int v = 0; v < 3; v++) {
            const float* pp = points + ((size_t)b * PP + vidx[v]) * 3;
            float x = __ldg(pp + 0) - cx, y = __ldg(pp + 1) - cy, z = __ldg(pp + 2) - cz;
            px[v] = r0 * x + r1 * y + r2 * z;
            py[v] = r3 * x + r4 * y + r5 * z;
            pz[v] = r6 * x + r7 * y + r8 * z;
        }

        float ax = px[1] - px[0], ay = py[1] - py[0], az = pz[1] - pz[0];
        float bx = px[2] - px[0], by = py[2] - py[0], bz = pz[2] - pz[0];
        float nx = ay * bz - az * by;
        float ny = az * bx - ax * bz;
        float nz = ax * by - ay * bx;

        float2 U0 = __ldg((const float2*)(uv + ((size_t)b * PP + i0) * 2));
        float2 U1 = __ldg((const float2*)(uv + ((size_t)b * PP + i1) * 2));
        float2 U2 = __ldg((const float2*)(uv + ((size_t)b * PP + i2) * 2));

        float4* fs = g_face + (size_t)idx * 4;
        fs[0] = make_float4(px[0], py[0], pz[0], px[1]);
        fs[1] = make_float4(py[1], pz[1], px[2], py[2]);
        fs[2] = make_float4(pz[2], U0.x, U0.y, U1.x);
        fs[3] = make_float4(U1.y, U2.x, U2.y, 0.0f);

        float len = sqrtf(nx * nx + ny * ny + nz * nz + 1e-8f) + 1e-15f;
        float inv = 1.0f / len;
        __stcs(out_normal + (size_t)idx * 3 + 0, nx * inv);
        __stcs(out_normal + (size_t)idx * 3 + 1, ny * inv);
        __stcs(out_normal + (size_t)idx * 3 + 2, nz * inv);
    }

    // ================= PHASE 2: device-wide barrier ========================
    // All GRID_BLOCKS are co-resident (launch_bounds guarantees 4 blocks/SM;
    // grid = 148*4), so spinning is deadlock-free. Generation counting makes
    // it replay-safe without a reset: each launch adds exactly GRID_BLOCKS
    // arrivals, and launches are sequential.
    __threadfence();
    __syncthreads();
    if (tid == 0) {
        unsigned int my = atomicAdd(&g_bar, 1u);
        unsigned int target = (my / GRID_BLOCKS + 1u) * GRID_BLOCKS;
        while (atomicAdd(&g_bar, 0u) < target) {
            __nanosleep(64);
        }
    }
    __syncthreads();
    __threadfence();

    // ================= PHASE 3: pixel shading ==============================
    __shared__ float4 sm[8 * 32 * 5];
    float4* sw = sm + warp * (32 * 5);

    for (int vb = blockIdx.x; vb < PIXEL_VB; vb += GRID_BLOCKS) {
        int idx = vb * 256 + tid;
        int b = idx >> 20;

        int face = __ldcs(pixface + idx);
        float prob = __ldcs(improb + idx);
        __stcs(out + (size_t)NPIX * 3 + idx, prob);   // improb passthrough

        float w0 = __ldcs(pixw + (size_t)idx * 3 + 0);
        float w1 = __ldcs(pixw + (size_t)idx * 3 + 1);
        float w2 = __ldcs(pixw + (size_t)idx * 3 + 2);

        float4 cAmb = __ldg(g_bconst + b * 4 + 0);
        float4 cDif = __ldg(g_bconst + b * 4 + 1);
        float4 cSpe = __ldg(g_bconst + b * 4 + 2);
        float4 cL   = __ldg(g_bconst + b * 4 + 3);
        float lx = cL.x, ly = cL.y, lz = cL.z;

        // warp-cooperative 64B struct gather (R10 shape)
        int sidx = b * FF + face;
        int src_pix = lane >> 2;
        int chunk = lane & 3;
        __syncwarp();                       // prior iteration's reads done
#pragma unroll
        for (int g = 0; g < 4; g++) {
            int p = g * 8 + src_pix;
            int s = __shfl_sync(0xffffffffu, sidx, p);
            float4 v = __ldg(g_face + (size_t)s * 4 + chunk);
            sw[p * 5 + chunk] = v;
        }
        __syncwarp();
        float4 f0 = sw[lane * 5 + 0];
        float4 f1 = sw[lane * 5 + 1];
        float4 f2 = sw[lane * 5 + 2];
        float4 f3 = sw[lane * 5 + 3];

        float p0x = f0.x, p0y = f0.y, p0z = f0.z;
        float p1x = f0.w, p1y = f1.x, p1z = f1.y;
        float p2x = f1.z, p2y = f1.w, p2z = f2.x;
        float u0x = f2.y, u0y = f2.z;
        float u1x = f2.w, u1y = f3.x;
        float u2x = f3.y, u2y = f3.z;

        // texcoords — canonical FMA accumulation chain (bit-exact)
        float tu = __fmaf_rn(w2, u2x, __fmaf_rn(w1, u1x, __fmul_rn(w0, u0x)));
        float tv = __fmaf_rn(w2, u2y, __fmaf_rn(w1, u1y, __fmul_rn(w0, u0y)));

        float fu = __fsub_rn(tu, floorf(tu));
        float fv = __fsub_rn(tv, floorf(tv));
        float x = __fsub_rn(__fmul_rn(fu, 2.0f), 1.0f);
        float yv = __fsub_rn(__fmul_rn(fv, 2.0f), 1.0f);
        float y = -yv;

        float fix = texindex(x, (float)TW);
        float fiy = texindex(y, (float)TH);
        int ix = (int)fix;
        int iy = (int)fiy;
        bool valid = (ix >= 0) && (ix < TW) && (iy >= 0) && (iy < TH);
        int ixc = min(max(ix, 0), TW - 1);
        int iyc = min(max(iy, 0), TH - 1);
        float vm = valid ? 1.0f : 0.0f;

        float4 t4 = __ldg(g_tex4 + (((size_t)b << 20) + iyc * TW + ixc));

        float ax = p1x - p0x, ay = p1y - p0y, az = p1z - p0z;
        float bx = p2x - p0x, by = p2y - p0y, bz = p2z - p0z;
        float nx = ay * bz - az * by;
        float ny = az * bx - ax * bz;
        float nz = ax * by - ay * bx;

        float ws = __fadd_rn(__fadd_rn(w0, w1), w2);

        float inx = nx * ws, iny = ny * ws, inz = nz * ws;
        float nlen = sqrtf(inx * inx + iny * iny + inz * inz + 1e-8f) + 1e-15f;
        float ninv = 1.0f / nlen;
        float n1x = inx * ninv, n1y = iny * ninv, n1z = inz * ninv;

        float ex = -(w0 * p0x + w1 * p1x + w2 * p2x);
        float ey = -(w0 * p0y + w1 * p1y + w2 * p2y);
        float ez = -(w0 * p0z + w1 * p1z + w2 * p2z);
        float elen = sqrtf(ex * ex + ey * ey + ez * ez + 1e-8f) + 1e-15f;
        float einv = 1.0f / elen;
        float e1x = ex * einv, e1y = ey * einv, e1z = ez * einv;

        float cosT = lx * n1x + ly * n1y + lz * n1z;
        cosT = fminf(fmaxf(cosT, 0.0f), 1.0f);
        float rx = -lx + 2.0f * cosT * n1x;
        float ry = -ly + 2.0f * cosT * n1y;
        float rz = -lz + 2.0f * cosT * n1z;
        float cosA = rx * e1x + ry * e1y + rz * e1z;
        cosA = fminf(fmaxf(cosA, 1e-5f), 1.0f);
        cosA = __powf(cosA, cAmb.w);

        float tr = t4.x * vm;
        float tg = t4.y * vm;
        float tb = t4.z * vm;

        float mprob = ws * prob;

        float cr = ((cAmb.x + cDif.x * cosT) * tr + cSpe.x * cosA) * mprob;
        float cg = ((cAmb.y + cDif.y * cosT) * tg + cSpe.y * cosA) * mprob;
        float cb = ((cAmb.z + cDif.z * cosT) * tb + cSpe.z * cosA) * mprob;
        cr = fminf(fmaxf(cr, 0.0f), 1.0f);
        cg = fminf(fmaxf(cg, 0.0f), 1.0f);
        cb = fminf(fmaxf(cb, 0.0f), 1.0f);

        __stcs(out + (size_t)idx * 3 + 0, cr);
        __stcs(out + (size_t)idx * 3 + 1, cg);
        __stcs(out + (size_t)idx * 3 + 2, cb);
    }
}

extern "C" void kernel_launch(void* const* d_in, const int* in_sizes, int n_in,
                              void* d_out, int out_size) {
    const float* points    = (const float*)d_in[0];   // (B,P,3)
    const int*   faces     = (const int*)  d_in[1];   // (F,3)
    const float* rot       = (const float*)d_in[2];   // (B,3,3)
    const float* cpos      = (const float*)d_in[3];   // (B,3)
    // d_in[4] = camera_proj (unused for outputs)
    const float* uv        = (const float*)d_in[5];   // (B,P,2)
    const float* texture   = (const float*)d_in[6];   // (B,3,TH,TW)
    const float* light     = (const float*)d_in[7];   // (B,3)
    const float* material  = (const float*)d_in[8];   // (B,3,3)
    const float* shininess = (const float*)d_in[9];   // (B,1)
    const int*   pixface   = (const int*)  d_in[10];  // (B,H,W)
    const float* pixw      = (const float*)d_in[11];  // (B,H,W,3)
    const float* improb    = (const float*)d_in[12];  // (B,H,W,1)

    float* out = (float*)d_out;

    fused_kernel<<<GRID_BLOCKS, 256>>>(
        points, faces, rot, cpos, uv, texture, light, material, shininess,
        pixface, pixw, improb, out);
}

// round 15
// speedup vs baseline: 1.1455x; 1.1455x over previous
#include <cuda_runtime.h>
#include <math.h>

#define BB 2
#define PP 50000
#define FF 100000
#define HH 1024
#define WW 1024
#define TH 1024
#define TW 1024

// Per-face feature struct: 4 x float4 = 64 bytes.
// [0]: p0.x p0.y p0.z p1.x
// [1]: p1.y p1.z p2.x p2.y
// [2]: p2.z u0.x u0.y u1.x
// [3]: u1.y u2.x u2.y pad
__device__ float4 g_face[BB * FF * 4];
// Interleaved texture: rgba per texel, 16B.
__device__ float4 g_tex4[BB * TH * TW];
// Per-batch packed constants:
// [b*4+0]: amb.rgb, shininess
// [b*4+1]: dif.rgb, 0
// [b*4+2]: spe.rgb, 0
// [b*4+3]: normalized light xyz, 0
__device__ float4 g_bconst[BB * 4];

#define NPIX (BB * HH * WW)                   // 2097152
#define FACE_N (BB * FF)
#define FACE_BLOCKS ((FACE_N + 255) / 256)    // 782
#define INTERLEAVE_BLOCKS (NPIX / 1024)       // 2048 (1024 texels/block, 4/thread)

// Face pass scheduled FIRST (latency-bound, overlaps with the
// bandwidth-bound interleave that follows).
__global__ void prep_kernel(const float* __restrict__ points,   // (B,P,3)
                            const int*   __restrict__ faces,    // (F,3)
                            const float* __restrict__ rot,      // (B,3,3)
                            const float* __restrict__ cpos,     // (B,3)
                            const float* __restrict__ uv,       // (B,P,2)
                            const float* __restrict__ texture,  // (B,3,TH,TW)
                            const float* __restrict__ light,    // (B,3)
                            const float* __restrict__ material, // (B,3,3)
                            const float* __restrict__ shininess,// (B,1)
                            float* __restrict__ out_normal)     // (B,F,3)
{
    if (blockIdx.x >= FACE_BLOCKS) {
        // ---- texture interleave, fully coalesced ----
        int base = (blockIdx.x - FACE_BLOCKS) * 1024 + threadIdx.x;
#pragma unroll
        for (int k = 0; k < 4; k++) {
            int t = base + k * 256;
            int b = t >> 20;                       // TH*TW = 1<<20
            int pos = t & (TH * TW - 1);
            size_t pbase = (size_t)b * 3 * TH * TW + pos;
            float r = __ldcs(texture + pbase);
            float g = __ldcs(texture + pbase + (size_t)TH * TW);
            float bl = __ldcs(texture + pbase + 2 * (size_t)TH * TW);
            g_tex4[t] = make_float4(r, g, bl, 0.0f);
        }
        return;
    }

    int idx = blockIdx.x * 256 + threadIdx.x;

    // per-batch constant packing (BB threads of the first block)
    if (blockIdx.x == 0 && threadIdx.x >= 256 - BB) {
        int b = threadIdx.x - (256 - BB);
        float lx = light[b * 3 + 0], ly = light[b * 3 + 1], lz = light[b * 3 + 2];
        float llen = sqrtf(lx * lx + ly * ly + lz * lz + 1e-8f) + 1e-15f;
        float linv = 1.0f / llen;
        const float* M = material + b * 9;
        g_bconst[b * 4 + 0] = make_float4(M[0], M[1], M[2], shininess[b]);
        g_bconst[b * 4 + 1] = make_float4(M[3], M[4], M[5], 0.0f);
        g_bconst[b * 4 + 2] = make_float4(M[6], M[7], M[8], 0.0f);
        g_bconst[b * 4 + 3] = make_float4(lx * linv, ly * linv, lz * linv, 0.0f);
    }

    if (idx >= FACE_N) return;
    int b = idx / FF;
    int f = idx - b * FF;

    // faces read once -> evict-first
    int i0 = __ldcs(faces + f * 3 + 0);
    int i1 = __ldcs(faces + f * 3 + 1);
    int i2 = __ldcs(faces + f * 3 + 2);

    float cx = cpos[b * 3 + 0], cy = cpos[b * 3 + 1], cz = cpos[b * 3 + 2];
    const float* R = rot + b * 9;
    float r0 = R[0], r1 = R[1], r2 = R[2];
    float r3 = R[3], r4 = R[4], r5 = R[5];
    float r6 = R[6], r7 = R[7], r8 = R[8];

    float px[3], py[3], pz[3];
    int vidx[3] = {i0, i1, i2};
#pragma unroll
    for (int v = 0; v < 3; v++) {
        const float* pp = points + ((size_t)b * PP + vidx[v]) * 3;
        float x = __ldg(pp + 0) - cx, y = __ldg(pp + 1) - cy, z = __ldg(pp + 2) - cz;
        px[v] = r0 * x + r1 * y + r2 * z;
        py[v] = r3 * x + r4 * y + r5 * z;
        pz[v] = r6 * x + r7 * y + r8 * z;
    }

    // normal = cross(p1-p0, p2-p0)
    float ax = px[1] - px[0], ay = py[1] - py[0], az = pz[1] - pz[0];
    float bx = px[2] - px[0], by = py[2] - py[0], bz = pz[2] - pz[0];
    float nx = ay * bz - az * by;
    float ny = az * bx - ax * bz;
    float nz = ax * by - ay * bx;

    float2 U0 = __ldg((const float2*)(uv + ((size_t)b * PP + i0) * 2));
    float2 U1 = __ldg((const float2*)(uv + ((size_t)b * PP + i1) * 2));
    float2 U2 = __ldg((const float2*)(uv + ((size_t)b * PP + i2) * 2));

    float4* fs = g_face + (size_t)idx * 4;
    fs[0] = make_float4(px[0], py[0], pz[0], px[1]);
    fs[1] = make_float4(py[1], pz[1], px[2], py[2]);
    fs[2] = make_float4(pz[2], U0.x, U0.y, U1.x);
    fs[3] = make_float4(U1.y, U2.x, U2.y, 0.0f);

    // normalized normal output: d / (sqrt(sum+1e-8) + 1e-15)
    float len = sqrtf(nx * nx + ny * ny + nz * nz + 1e-8f) + 1e-15f;
    float inv = 1.0f / len;
    __stcs(out_normal + (size_t)idx * 3 + 0, nx * inv);
    __stcs(out_normal + (size_t)idx * 3 + 1, ny * inv);
    __stcs(out_normal + (size_t)idx * 3 + 2, nz * inv);
}

// Exact nearest texel index chain; every multiply is by a power of two so this
// is contraction-insensitive.
__device__ __forceinline__ float texindex(float x, float T) {
    float t = __fadd_rn(x, 1.0f);
    t = __fmul_rn(t, T);
    t = __fsub_rn(t, 1.0f);
    t = __fmul_rn(t, 0.5f);
    t = __fadd_rn(t, 0.5f);
    return floorf(t);
}

__global__ void __launch_bounds__(256) pixel_kernel(
                             const int*   __restrict__ pixface,   // (B,H,W)
                             const float* __restrict__ pixw,      // (B,H,W,3)
                             const float* __restrict__ improb,    // (B,H,W,1)
                             float* __restrict__ out)             // flat
{
    int idx = blockIdx.x * 256 + threadIdx.x;
    int b = idx >> 20;    // HH*WW = 1<<20

    int lane = threadIdx.x & 31;
    int warp = threadIdx.x >> 5;

    // ---- PDL prologue: everything here is independent of prep_kernel ----
    // (streaming inputs + improb passthrough write into a region prep never
    // touches). This runs while prep's tail drains.
    int face = __ldcs(pixface + idx);
    float prob = __ldcs(improb + idx);
    __stcs(out + (size_t)NPIX * 3 + idx, prob);   // improb passthrough

    float w0 = __ldcs(pixw + (size_t)idx * 3 + 0);
    float w1 = __ldcs(pixw + (size_t)idx * 3 + 1);
    float w2 = __ldcs(pixw + (size_t)idx * 3 + 2);

    // ---- wait for prep_kernel completion (implicit trigger) before touching
    // g_bconst / g_face / g_tex4 ----
#if defined(__CUDA_ARCH__) && __CUDA_ARCH__ >= 900
    cudaGridDependencySynchronize();
#endif

    // per-batch packed constants (broadcast loads)
    float4 cAmb = __ldg(g_bconst + b * 4 + 0);   // amb.rgb, shininess
    float4 cDif = __ldg(g_bconst + b * 4 + 1);
    float4 cSpe = __ldg(g_bconst + b * 4 + 2);
    float4 cL   = __ldg(g_bconst + b * 4 + 3);   // normalized light
    float lx = cL.x, ly = cL.y, lz = cL.z;

    // ---- warp-cooperative 64B struct gather (R10 shape) ----
    __shared__ float4 sm[8 * 32 * 5];
    float4* sw = sm + warp * (32 * 5);

    int sidx = b * FF + face;           // struct index for this pixel
    int src_pix = lane >> 2;            // which pixel of the group of 8
    int chunk = lane & 3;               // which float4 of that struct
#pragma unroll
    for (int g = 0; g < 4; g++) {
        int p = g * 8 + src_pix;
        int s = __shfl_sync(0xffffffffu, sidx, p);
        float4 v = __ldg(g_face + (size_t)s * 4 + chunk);
        sw[p * 5 + chunk] = v;
    }
    __syncwarp();
    float4 f0 = sw[lane * 5 + 0];
    float4 f1 = sw[lane * 5 + 1];
    float4 f2 = sw[lane * 5 + 2];
    float4 f3 = sw[lane * 5 + 3];

    // unpack
    float p0x = f0.x, p0y = f0.y, p0z = f0.z;
    float p1x = f0.w, p1y = f1.x, p1z = f1.y;
    float p2x = f1.z, p2y = f1.w, p2z = f2.x;
    float u0x = f2.y, u0y = f2.z;
    float u1x = f2.w, u1y = f3.x;
    float u2x = f3.y, u2y = f3.z;

    // texcoords — canonical FMA accumulation chain (bit-exact vs reference);
    // computed first so the texture load issues ASAP.
    float tu = __fmaf_rn(w2, u2x, __fmaf_rn(w1, u1x, __fmul_rn(w0, u0x)));
    float tv = __fmaf_rn(w2, u2y, __fmaf_rn(w1, u1y, __fmul_rn(w0, u0y)));

    float fu = __fsub_rn(tu, floorf(tu));
    float fv = __fsub_rn(tv, floorf(tv));
    float x = __fsub_rn(__fmul_rn(fu, 2.0f), 1.0f);
    float yv = __fsub_rn(__fmul_rn(fv, 2.0f), 1.0f);
    float y = -yv;

    float fix = texindex(x, (float)TW);
    float fiy = texindex(y, (float)TH);
    int ix = (int)fix;
    int iy = (int)fiy;
    bool valid = (ix >= 0) && (ix < TW) && (iy >= 0) && (iy < TH);
    int ixc = min(max(ix, 0), TW - 1);
    int iyc = min(max(iy, 0), TH - 1);
    float vm = valid ? 1.0f : 0.0f;

    float4 t4 = __ldg(g_tex4 + (((size_t)b << 20) + iyc * TW + ixc));

    // recompute face normal (continuous path; FMA ok)
    float ax = p1x - p0x, ay = p1y - p0y, az = p1z - p0z;
    float bx = p2x - p0x, by = p2y - p0y, bz = p2z - p0z;
    float nx = ay * bz - az * by;
    float ny = az * bx - ax * bz;
    float nz = ax * by - ay * bx;

    float ws = __fadd_rn(__fadd_rn(w0, w1), w2);

    // imnormal = ws * n ; normalize
    float inx = nx * ws, iny = ny * ws, inz = nz * ws;
    float nlen = sqrtf(inx * inx + iny * iny + inz * inz + 1e-8f) + 1e-15f;
    float ninv = 1.0f / nlen;
    float n1x = inx * ninv, n1y = iny * ninv, n1z = inz * ninv;

    // imeye = -(w0*p0 + w1*p1 + w2*p2) ; normalize
    float ex = -(w0 * p0x + w1 * p1x + w2 * p2x);
    float ey = -(w0 * p0y + w1 * p1y + w2 * p2y);
    float ez = -(w0 * p0z + w1 * p1z + w2 * p2z);
    float elen = sqrtf(ex * ex + ey * ey + ez * ez + 1e-8f) + 1e-15f;
    float einv = 1.0f / elen;
    float e1x = ex * einv, e1y = ey * einv, e1z = ez * einv;

    // phong
    float cosT = lx * n1x + ly * n1y + lz * n1z;
    cosT = fminf(fmaxf(cosT, 0.0f), 1.0f);
    float rx = -lx + 2.0f * cosT * n1x;
    float ry = -ly + 2.0f * cosT * n1y;
    float rz = -lz + 2.0f * cosT * n1z;
    float cosA = rx * e1x + ry * e1y + rz * e1z;
    cosA = fminf(fmaxf(cosA, 1e-5f), 1.0f);
    cosA = __powf(cosA, cAmb.w);   // fast pow: ~6e-6 rel err on spe term

    float tr = t4.x * vm;
    float tg = t4.y * vm;
    float tb = t4.z * vm;

    float mprob = ws * prob;

    float cr = ((cAmb.x + cDif.x * cosT) * tr + cSpe.x * cosA) * mprob;
    float cg = ((cAmb.y + cDif.y * cosT) * tg + cSpe.y * cosA) * mprob;
    float cb = ((cAmb.z + cDif.z * cosT) * tb + cSpe.z * cosA) * mprob;
    cr = fminf(fmaxf(cr, 0.0f), 1.0f);
    cg = fminf(fmaxf(cg, 0.0f), 1.0f);
    cb = fminf(fmaxf(cb, 0.0f), 1.0f);

    __stcs(out + (size_t)idx * 3 + 0, cr);
    __stcs(out + (size_t)idx * 3 + 1, cg);
    __stcs(out + (size_t)idx * 3 + 2, cb);
}

extern "C" void kernel_launch(void* const* d_in, const int* in_sizes, int n_in,
                              void* d_out, int out_size) {
    const float* points    = (const float*)d_in[0];   // (B,P,3)
    const int*   faces     = (const int*)  d_in[1];   // (F,3)
    const float* rot       = (const float*)d_in[2];   // (B,3,3)
    const float* cpos      = (const float*)d_in[3];   // (B,3)
    // d_in[4] = camera_proj (unused for outputs)
    const float* uv        = (const float*)d_in[5];   // (B,P,2)
    const float* texture   = (const float*)d_in[6];   // (B,3,TH,TW)
    const float* light     = (const float*)d_in[7];   // (B,3)
    const float* material  = (const float*)d_in[8];   // (B,3,3)
    const float* shininess = (const float*)d_in[9];   // (B,1)
    const int*   pixface   = (const int*)  d_in[10];  // (B,H,W)
    const float* pixw      = (const float*)d_in[11];  // (B,H,W,3)
    const float* improb    = (const float*)d_in[12];  // (B,H,W,1)

    float* out = (float*)d_out;
    // output layout: [imrender B*H*W*3][improb B*H*W][normal1 B*F*3]
    float* out_normal = out + (size_t)NPIX * 3 + NPIX;

    prep_kernel<<<FACE_BLOCKS + INTERLEAVE_BLOCKS, 256>>>(
        points, faces, rot, cpos, uv, texture, light, material, shininess,
        out_normal);

    // PDL launch: pixel_kernel's prologue overlaps prep's tail; the
    // cudaGridDependencySynchronize() inside gates prep-dependent reads.
    {
        cudaLaunchConfig_t cfg = {};
        cfg.gridDim  = dim3(NPIX / 256);
        cfg.blockDim = dim3(256);
        cudaLaunchAttribute attrs[1];
        attrs[0].id = cudaLaunchAttributeProgrammaticStreamSerialization;
        attrs[0].val.programmaticStreamSerializationAllowed = 1;
        cfg.attrs = attrs;
        cfg.numAttrs = 1;
        cudaLaunchKernelEx(&cfg, pixel_kernel, pixface, pixw, improb, out);
    }
}

// round 16
// speedup vs baseline: 1.1834x; 1.0331x over previous
#include <cuda_runtime.h>
#include <cuda_fp16.h>
#include <math.h>

#define BB 2
#define PP 50000
#define FF 100000
#define HH 1024
#define WW 1024
#define TH 1024
#define TW 1024

// Per-face feature struct: 4 x float4 = 64 bytes.
// [0]: p0.x p0.y p0.z p1.x
// [1]: p1.y p1.z p2.x p2.y
// [2]: p2.z u0.x u0.y u1.x
// [3]: u1.y u2.x u2.y pad
__device__ float4 g_face[BB * FF * 4];
// Interleaved texture: half4 {r,g | b,0} per texel, 8B. Texel VALUES feed only
// the continuous color path (tolerance 1e-3); the index chain stays float.
__device__ uint2 g_texh[BB * TH * TW];
// Per-batch packed constants:
// [b*4+0]: amb.rgb, shininess
// [b*4+1]: dif.rgb, 0
// [b*4+2]: spe.rgb, 0
// [b*4+3]: normalized light xyz, 0
__device__ float4 g_bconst[BB * 4];

#define NPIX (BB * HH * WW)                   // 2097152
#define FACE_N (BB * FF)
#define FACE_BLOCKS ((FACE_N + 255) / 256)    // 782
#define INTERLEAVE_BLOCKS (NPIX / 1024)       // 2048 (1024 texels/block, 4/thread)

// Face pass scheduled FIRST (latency-bound, overlaps with the
// bandwidth-bound interleave that follows).
__global__ void prep_kernel(const float* __restrict__ points,   // (B,P,3)
                            const int*   __restrict__ faces,    // (F,3)
                            const float* __restrict__ rot,      // (B,3,3)
                            const float* __restrict__ cpos,     // (B,3)
                            const float* __restrict__ uv,       // (B,P,2)
                            const float* __restrict__ texture,  // (B,3,TH,TW)
                            const float* __restrict__ light,    // (B,3)
                            const float* __restrict__ material, // (B,3,3)
                            const float* __restrict__ shininess,// (B,1)
                            float* __restrict__ out_normal)     // (B,F,3)
{
    if (blockIdx.x >= FACE_BLOCKS) {
        // ---- texture interleave, fully coalesced, half4 output ----
        int base = (blockIdx.x - FACE_BLOCKS) * 1024 + threadIdx.x;
#pragma unroll
        for (int k = 0; k < 4; k++) {
            int t = base + k * 256;
            int b = t >> 20;                       // TH*TW = 1<<20
            int pos = t & (TH * TW - 1);
            size_t pbase = (size_t)b * 3 * TH * TW + pos;
            float r = __ldcs(texture + pbase);
            float g = __ldcs(texture + pbase + (size_t)TH * TW);
            float bl = __ldcs(texture + pbase + 2 * (size_t)TH * TW);
            __half2 rg = __floats2half2_rn(r, g);
            __half2 b0 = __floats2half2_rn(bl, 0.0f);
            uint2 packed;
            packed.x = *(unsigned int*)&rg;
            packed.y = *(unsigned int*)&b0;
            g_texh[t] = packed;
        }
        return;
    }

    int idx = blockIdx.x * 256 + threadIdx.x;

    // per-batch constant packing (BB threads of the first block)
    if (blockIdx.x == 0 && threadIdx.x >= 256 - BB) {
        int b = threadIdx.x - (256 - BB);
        float lx = light[b * 3 + 0], ly = light[b * 3 + 1], lz = light[b * 3 + 2];
        float llen = sqrtf(lx * lx + ly * ly + lz * lz + 1e-8f) + 1e-15f;
        float linv = 1.0f / llen;
        const float* M = material + b * 9;
        g_bconst[b * 4 + 0] = make_float4(M[0], M[1], M[2], shininess[b]);
        g_bconst[b * 4 + 1] = make_float4(M[3], M[4], M[5], 0.0f);
        g_bconst[b * 4 + 2] = make_float4(M[6], M[7], M[8], 0.0f);
        g_bconst[b * 4 + 3] = make_float4(lx * linv, ly * linv, lz * linv, 0.0f);
    }

    if (idx >= FACE_N) return;
    int b = idx / FF;
    int f = idx - b * FF;

    // faces read once -> evict-first
    int i0 = __ldcs(faces + f * 3 + 0);
    int i1 = __ldcs(faces + f * 3 + 1);
    int i2 = __ldcs(faces + f * 3 + 2);

    float cx = cpos[b * 3 + 0], cy = cpos[b * 3 + 1], cz = cpos[b * 3 + 2];
    const float* R = rot + b * 9;
    float r0 = R[0], r1 = R[1], r2 = R[2];
    float r3 = R[3], r4 = R[4], r5 = R[5];
    float r6 = R[6], r7 = R[7], r8 = R[8];

    float px[3], py[3], pz[3];
    int vidx[3] = {i0, i1, i2};
#pragma unroll
    for (int v = 0; v < 3; v++) {
        const float* pp = points + ((size_t)b * PP + vidx[v]) * 3;
        float x = __ldg(pp + 0) - cx, y = __ldg(pp + 1) - cy, z = __ldg(pp + 2) - cz;
        px[v] = r0 * x + r1 * y + r2 * z;
        py[v] = r3 * x + r4 * y + r5 * z;
        pz[v] = r6 * x + r7 * y + r8 * z;
    }

    // normal = cross(p1-p0, p2-p0)
    float ax = px[1] - px[0], ay = py[1] - py[0], az = pz[1] - pz[0];
    float bx = px[2] - px[0], by = py[2] - py[0], bz = pz[2] - pz[0];
    float nx = ay * bz - az * by;
    float ny = az * bx - ax * bz;
    float nz = ax * by - ay * bx;

    float2 U0 = __ldg((const float2*)(uv + ((size_t)b * PP + i0) * 2));
    float2 U1 = __ldg((const float2*)(uv + ((size_t)b * PP + i1) * 2));
    float2 U2 = __ldg((const float2*)(uv + ((size_t)b * PP + i2) * 2));

    float4* fs = g_face + (size_t)idx * 4;
    fs[0] = make_float4(px[0], py[0], pz[0], px[1]);
    fs[1] = make_float4(py[1], pz[1], px[2], py[2]);
    fs[2] = make_float4(pz[2], U0.x, U0.y, U1.x);
    fs[3] = make_float4(U1.y, U2.x, U2.y, 0.0f);

    // normalized normal output: d / (sqrt(sum+1e-8) + 1e-15)
    float len = sqrtf(nx * nx + ny * ny + nz * nz + 1e-8f) + 1e-15f;
    float inv = 1.0f / len;
    __stcs(out_normal + (size_t)idx * 3 + 0, nx * inv);
    __stcs(out_normal + (size_t)idx * 3 + 1, ny * inv);
    __stcs(out_normal + (size_t)idx * 3 + 2, nz * inv);
}

// Exact nearest texel index chain; every multiply is by a power of two so this
// is contraction-insensitive.
__device__ __forceinline__ float texindex(float x, float T) {
    float t = __fadd_rn(x, 1.0f);
    t = __fmul_rn(t, T);
    t = __fsub_rn(t, 1.0f);
    t = __fmul_rn(t, 0.5f);
    t = __fadd_rn(t, 0.5f);
    return floorf(t);
}

__global__ void __launch_bounds__(256) pixel_kernel(
                             const int*   __restrict__ pixface,   // (B,H,W)
                             const float* __restrict__ pixw,      // (B,H,W,3)
                             const float* __restrict__ improb,    // (B,H,W,1)
                             float* __restrict__ out)             // flat
{
    int idx = blockIdx.x * 256 + threadIdx.x;
    int b = idx >> 20;    // HH*WW = 1<<20

    int lane = threadIdx.x & 31;
    int warp = threadIdx.x >> 5;

    // ---- PDL prologue: everything here is independent of prep_kernel ----
    int face = __ldcs(pixface + idx);
    float prob = __ldcs(improb + idx);
    __stcs(out + (size_t)NPIX * 3 + idx, prob);   // improb passthrough

    float w0 = __ldcs(pixw + (size_t)idx * 3 + 0);
    float w1 = __ldcs(pixw + (size_t)idx * 3 + 1);
    float w2 = __ldcs(pixw + (size_t)idx * 3 + 2);

    // ---- wait for prep_kernel completion before touching prep outputs ----
#if defined(__CUDA_ARCH__) && __CUDA_ARCH__ >= 900
    cudaGridDependencySynchronize();
#endif

    // per-batch packed constants (broadcast loads)
    float4 cAmb = __ldg(g_bconst + b * 4 + 0);   // amb.rgb, shininess
    float4 cDif = __ldg(g_bconst + b * 4 + 1);
    float4 cSpe = __ldg(g_bconst + b * 4 + 2);
    float4 cL   = __ldg(g_bconst + b * 4 + 3);   // normalized light
    float lx = cL.x, ly = cL.y, lz = cL.z;

    // ---- warp-cooperative 64B struct gather (R10 shape) ----
    __shared__ float4 sm[8 * 32 * 5];
    float4* sw = sm + warp * (32 * 5);

    int sidx = b * FF + face;           // struct index for this pixel
    int src_pix = lane >> 2;            // which pixel of the group of 8
    int chunk = lane & 3;               // which float4 of that struct
#pragma unroll
    for (int g = 0; g < 4; g++) {
        int p = g * 8 + src_pix;
        int s = __shfl_sync(0xffffffffu, sidx, p);
        float4 v = __ldg(g_face + (size_t)s * 4 + chunk);
        sw[p * 5 + chunk] = v;
    }
    __syncwarp();
    float4 f0 = sw[lane * 5 + 0];
    float4 f1 = sw[lane * 5 + 1];
    float4 f2 = sw[lane * 5 + 2];
    float4 f3 = sw[lane * 5 + 3];

    // unpack
    float p0x = f0.x, p0y = f0.y, p0z = f0.z;
    float p1x = f0.w, p1y = f1.x, p1z = f1.y;
    float p2x = f1.z, p2y = f1.w, p2z = f2.x;
    float u0x = f2.y, u0y = f2.z;
    float u1x = f2.w, u1y = f3.x;
    float u2x = f3.y, u2y = f3.z;

    // texcoords — canonical FMA accumulation chain (bit-exact vs reference);
    // computed first so the texture load issues ASAP.
    float tu = __fmaf_rn(w2, u2x, __fmaf_rn(w1, u1x, __fmul_rn(w0, u0x)));
    float tv = __fmaf_rn(w2, u2y, __fmaf_rn(w1, u1y, __fmul_rn(w0, u0y)));

    float fu = __fsub_rn(tu, floorf(tu));
    float fv = __fsub_rn(tv, floorf(tv));
    float x = __fsub_rn(__fmul_rn(fu, 2.0f), 1.0f);
    float yv = __fsub_rn(__fmul_rn(fv, 2.0f), 1.0f);
    float y = -yv;

    float fix = texindex(x, (float)TW);
    float fiy = texindex(y, (float)TH);
    int ix = (int)fix;
    int iy = (int)fiy;
    bool valid = (ix >= 0) && (ix < TW) && (iy >= 0) && (iy < TH);
    int ixc = min(max(ix, 0), TW - 1);
    int iyc = min(max(iy, 0), TH - 1);
    float vm = valid ? 1.0f : 0.0f;

    uint2 th = __ldg(g_texh + (((size_t)b << 20) + iyc * TW + ixc));
    __half2 rg = *(__half2*)&th.x;
    __half2 b0h = *(__half2*)&th.y;
    float tr0 = __low2float(rg);
    float tg0 = __high2float(rg);
    float tb0 = __low2float(b0h);

    // recompute face normal (continuous path; FMA ok)
    float ax = p1x - p0x, ay = p1y - p0y, az = p1z - p0z;
    float bx = p2x - p0x, by = p2y - p0y, bz = p2z - p0z;
    float nx = ay * bz - az * by;
    float ny = az * bx - ax * bz;
    float nz = ax * by - ay * bx;

    float ws = __fadd_rn(__fadd_rn(w0, w1), w2);

    // imnormal = ws * n ; normalize
    float inx = nx * ws, iny = ny * ws, inz = nz * ws;
    float nlen = sqrtf(inx * inx + iny * iny + inz * inz + 1e-8f) + 1e-15f;
    float ninv = 1.0f / nlen;
    float n1x = inx * ninv, n1y = iny * ninv, n1z = inz * ninv;

    // imeye = -(w0*p0 + w1*p1 + w2*p2) ; normalize
    float ex = -(w0 * p0x + w1 * p1x + w2 * p2x);
    float ey = -(w0 * p0y + w1 * p1y + w2 * p2y);
    float ez = -(w0 * p0z + w1 * p1z + w2 * p2z);
    float elen = sqrtf(ex * ex + ey * ey + ez * ez + 1e-8f) + 1e-15f;
    float einv = 1.0f / elen;
    float e1x = ex * einv, e1y = ey * einv, e1z = ez * einv;

    // phong
    float cosT = lx * n1x + ly * n1y + lz * n1z;
    cosT = fminf(fmaxf(cosT, 0.0f), 1.0f);
    float rx = -lx + 2.0f * cosT * n1x;
    float ry = -ly + 2.0f * cosT * n1y;
    float rz = -lz + 2.0f * cosT * n1z;
    float cosA = rx * e1x + ry * e1y + rz * e1z;
    cosA = fminf(fmaxf(cosA, 1e-5f), 1.0f);
    cosA = __powf(cosA, cAmb.w);   // fast pow: ~6e-6 rel err on spe term

    float tr = tr0 * vm;
    float tg = tg0 * vm;
    float tb = tb0 * vm;

    float mprob = ws * prob;

    float cr = ((cAmb.x + cDif.x * cosT) * tr + cSpe.x * cosA) * mprob;
    float cg = ((cAmb.y + cDif.y * cosT) * tg + cSpe.y * cosA) * mprob;
    float cb = ((cAmb.z + cDif.z * cosT) * tb + cSpe.z * cosA) * mprob;
    cr = fminf(fmaxf(cr, 0.0f), 1.0f);
    cg = fminf(fmaxf(cg, 0.0f), 1.0f);
    cb = fminf(fmaxf(cb, 0.0f), 1.0f);

    __stcs(out + (size_t)idx * 3 + 0, cr);
    __stcs(out + (size_t)idx * 3 + 1, cg);
    __stcs(out + (size_t)idx * 3 + 2, cb);
}

extern "C" void kernel_launch(void* const* d_in, const int* in_sizes, int n_in,
                              void* d_out, int out_size) {
    const float* points    = (const float*)d_in[0];   // (B,P,3)
    const int*   faces     = (const int*)  d_in[1];   // (F,3)
    const float* rot       = (const float*)d_in[2];   // (B,3,3)
    const float* cpos      = (const float*)d_in[3];   // (B,3)
    // d_in[4] = camera_proj (unused for outputs)
    const float* uv        = (const float*)d_in[5];   // (B,P,2)
    const float* texture   = (const float*)d_in[6];   // (B,3,TH,TW)
    const float* light     = (const float*)d_in[7];   // (B,3)
    const float* material  = (const float*)d_in[8];   // (B,3,3)
    const float* shininess = (const float*)d_in[9];   // (B,1)
    const int*   pixface   = (const int*)  d_in[10];  // (B,H,W)
    const float* pixw      = (const float*)d_in[11];  // (B,H,W,3)
    const float* improb    = (const float*)d_in[12];  // (B,H,W,1)

    float* out = (float*)d_out;
    // output layout: [imrender B*H*W*3][improb B*H*W][normal1 B*F*3]
    float* out_normal = out + (size_t)NPIX * 3 + NPIX;

    prep_kernel<<<FACE_BLOCKS + INTERLEAVE_BLOCKS, 256>>>(
        points, faces, rot, cpos, uv, texture, light, material, shininess,
        out_normal);

    // PDL launch: pixel_kernel's prologue overlaps prep's tail; the
    // cudaGridDependencySynchronize() inside gates prep-dependent reads.
    {
        cudaLaunchConfig_t cfg = {};
        cfg.gridDim  = dim3(NPIX / 256);
        cfg.blockDim = dim3(256);
        cudaLaunchAttribute attrs[1];
        attrs[0].id = cudaLaunchAttributeProgrammaticStreamSerialization;
        attrs[0].val.programmaticStreamSerializationAllowed = 1;
        cfg.attrs = attrs;
        cfg.numAttrs = 1;
        cudaLaunchKernelEx(&cfg, pixel_kernel, pixface, pixw, improb, out);
    }
}